// round 3
// baseline (speedup 1.0000x reference)
#include <cuda_runtime.h>

#define BB 64
#define TT 577
#define DD 768
#define DENS 519      // int(577*0.9)
#define NSKIP 58      // 577 - 519
#define D4 (DD/4)     // 192 float4 per row
#define RPB 4         // source rows per scatter block

// Scratch (no device allocation allowed)
__device__ float g_logits[BB*TT];
__device__ int   g_rank[BB*TT];      // rank (descending, stable) of each source row
__device__ int   g_skip[BB*NSKIP];   // per batch: skipped source indices, ascending prob order
__device__ float g_weights[BB*NSKIP];

// ---------------- Kernel 1: logits = x @ w + b  (one warp per TWO rows) ----------------
__global__ void logits_kernel(const float* __restrict__ x,
                              const float* __restrict__ w,
                              const float* __restrict__ bias) {
    int warpsPerBlock = blockDim.x >> 5;
    int warpId = threadIdx.x >> 5;
    int lane   = threadIdx.x & 31;
    int pair = blockIdx.x * warpsPerBlock + warpId;   // handles rows 2*pair, 2*pair+1
    int row0 = pair * 2;
    if (row0 >= BB*TT) return;

    const float4* xr0 = reinterpret_cast<const float4*>(x) + (size_t)row0 * D4;
    const float4* xr1 = xr0 + D4;
    const float4* w4  = reinterpret_cast<const float4*>(w);

    float4 a0[6], a1[6], wv[6];
    #pragma unroll
    for (int k = 0; k < 6; k++) a0[k] = xr0[k*32 + lane];
    #pragma unroll
    for (int k = 0; k < 6; k++) a1[k] = xr1[k*32 + lane];
    #pragma unroll
    for (int k = 0; k < 6; k++) wv[k] = __ldg(&w4[k*32 + lane]);

    float acc0 = 0.f, acc1 = 0.f;
    #pragma unroll
    for (int k = 0; k < 6; k++) {
        acc0 = fmaf(a0[k].x, wv[k].x, acc0);
        acc0 = fmaf(a0[k].y, wv[k].y, acc0);
        acc0 = fmaf(a0[k].z, wv[k].z, acc0);
        acc0 = fmaf(a0[k].w, wv[k].w, acc0);
        acc1 = fmaf(a1[k].x, wv[k].x, acc1);
        acc1 = fmaf(a1[k].y, wv[k].y, acc1);
        acc1 = fmaf(a1[k].z, wv[k].z, acc1);
        acc1 = fmaf(a1[k].w, wv[k].w, acc1);
    }
    #pragma unroll
    for (int off = 16; off; off >>= 1) {
        acc0 += __shfl_xor_sync(0xffffffffu, acc0, off);
        acc1 += __shfl_xor_sync(0xffffffffu, acc1, off);
    }
    if (lane == 0) {
        float bv = bias[0];
        g_logits[row0]     = acc0 + bv;
        g_logits[row0 + 1] = acc1 + bv;
    }
}

// ---------------- Kernel 2: rank (stable) + skip softmax ----------------
__global__ void rank_kernel() {
    __shared__ float s[TT];
    __shared__ float skipP[NSKIP];
    __shared__ float skipE[NSKIP];

    int b = blockIdx.x;
    int i = threadIdx.x;

    if (i < TT) s[i] = g_logits[b*TT + i];
    __syncthreads();

    if (i < TT) {
        float my = s[i];
        int rank = 0;
        #pragma unroll 8
        for (int j = 0; j < TT; j++) {
            float v = s[j];
            rank += (v > my) || (v == my && j < i);  // stable: lower index wins
        }
        g_rank[b*TT + i] = rank;
        if (rank >= DENS) {
            int pos = (TT - 1) - rank;               // ascending skipped order
            g_skip[b*NSKIP + pos] = i;
            skipP[pos] = 1.f / (1.f + expf(-my));    // sigmoid prob
        }
    }
    __syncthreads();

    if (i < NSKIP) {
        float m = -1e30f;
        #pragma unroll
        for (int j = 0; j < NSKIP; j++) m = fmaxf(m, skipP[j]);
        skipE[i] = expf(skipP[i] - m);
    }
    __syncthreads();

    if (i < NSKIP) {
        float sum = 0.f;
        #pragma unroll
        for (int j = 0; j < NSKIP; j++) sum += skipE[j];
        g_weights[b*NSKIP + i] = skipE[i] / sum;
    }
}

// ---------------- Kernel 3: scatter (sequential reads, permuted writes) ----------------
__global__ void scatter_kernel(const float* __restrict__ x, float* __restrict__ out) {
    int base = blockIdx.x * RPB;      // first source row (global index b*TT+t)
    int tid  = threadIdx.x;           // 0..191

    const float4* xin = reinterpret_cast<const float4*>(x);
    float4* o4 = reinterpret_cast<float4*>(out);
    const size_t skipBase = (size_t)BB * DENS * D4;

    // Front-batched independent loads (MLP=4)
    float4 v[RPB];
    #pragma unroll
    for (int r = 0; r < RPB; r++)
        v[r] = xin[((size_t)(base + r)) * D4 + tid];

    #pragma unroll
    for (int r = 0; r < RPB; r++) {
        int src = base + r;
        int b = src / TT;
        int rank = g_rank[src];
        size_t off = (rank < DENS)
            ? ((size_t)(b*DENS + rank) * D4)
            : (skipBase + (size_t)(b*NSKIP + ((TT-1) - rank)) * D4);
        // streaming store: evict-first, keep x resident in L2
        __stcs(&o4[off + tid], v[r]);
    }
}

// ---------------- Kernel 4: summary token (weighted sum of skipped rows) ----------------
__global__ void summary_kernel(const float* __restrict__ x, float* __restrict__ out) {
    int b   = blockIdx.x;
    int tid = threadIdx.x;            // 0..191

    const float4* xin = reinterpret_cast<const float4*>(x);
    float4* o4 = reinterpret_cast<float4*>(out);
    const size_t sumBase = (size_t)BB * (DENS + NSKIP) * D4;

    float4 acc = make_float4(0.f, 0.f, 0.f, 0.f);
    #pragma unroll 2
    for (int sI = 0; sI < NSKIP; sI++) {
        int src = g_skip[b*NSKIP + sI];
        float wgt = g_weights[b*NSKIP + sI];
        float4 vv = xin[((size_t)b*TT + src) * D4 + tid];
        acc.x = fmaf(wgt, vv.x, acc.x);
        acc.y = fmaf(wgt, vv.y, acc.y);
        acc.z = fmaf(wgt, vv.z, acc.z);
        acc.w = fmaf(wgt, vv.w, acc.w);
    }
    o4[sumBase + (size_t)b * D4 + tid] = acc;
}

extern "C" void kernel_launch(void* const* d_in, const int* in_sizes, int n_in,
                              void* d_out, int out_size) {
    const float* x    = (const float*)d_in[0];
    const float* w    = (const float*)d_in[1];
    const float* bias = (const float*)d_in[2];
    float* out = (float*)d_out;

    int rows = BB * TT;               // 36928
    // 1) logits: 2 rows per warp, 8 warps/block
    logits_kernel<<<(rows/2 + 7) / 8, 256>>>(x, w, bias);
    // 2) rank + softmax
    rank_kernel<<<BB, 608>>>();
    // 3) scatter: 4 sequential source rows per block
    scatter_kernel<<<rows / RPB, 192>>>(x, out);
    // 4) summary tokens
    summary_kernel<<<BB, 192>>>(x, out);
}

// round 4
// speedup vs baseline: 1.2226x; 1.2226x over previous
#include <cuda_runtime.h>

#define BB 64
#define TT 577
#define DD 768
#define DENS 519      // int(577*0.9)
#define NSKIP 58      // 577 - 519
#define D4 (DD/4)     // 192 float4 per row
#define RPB 8         // source rows per scatter block

// Scratch (no device allocation allowed)
__device__ float g_logits[BB*TT];
__device__ int   g_rank[BB*TT];      // rank (descending, stable) of each source row
__device__ int   g_skip[BB*NSKIP];   // per batch: skipped source indices, ascending prob order
__device__ float g_weights[BB*NSKIP];

// ---------------- Kernel 1: logits = x @ w + b  (one warp per TWO rows) ----------------
__global__ void logits_kernel(const float* __restrict__ x,
                              const float* __restrict__ w,
                              const float* __restrict__ bias) {
    int warpsPerBlock = blockDim.x >> 5;
    int warpId = threadIdx.x >> 5;
    int lane   = threadIdx.x & 31;
    int pair = blockIdx.x * warpsPerBlock + warpId;
    int row0 = pair * 2;
    if (row0 >= BB*TT) return;

    const float4* xr0 = reinterpret_cast<const float4*>(x) + (size_t)row0 * D4;
    const float4* xr1 = xr0 + D4;
    const float4* w4  = reinterpret_cast<const float4*>(w);

    float4 a0[6], a1[6], wv[6];
    #pragma unroll
    for (int k = 0; k < 6; k++) a0[k] = xr0[k*32 + lane];
    #pragma unroll
    for (int k = 0; k < 6; k++) a1[k] = xr1[k*32 + lane];
    #pragma unroll
    for (int k = 0; k < 6; k++) wv[k] = __ldg(&w4[k*32 + lane]);

    float acc0 = 0.f, acc1 = 0.f;
    #pragma unroll
    for (int k = 0; k < 6; k++) {
        acc0 = fmaf(a0[k].x, wv[k].x, acc0);
        acc0 = fmaf(a0[k].y, wv[k].y, acc0);
        acc0 = fmaf(a0[k].z, wv[k].z, acc0);
        acc0 = fmaf(a0[k].w, wv[k].w, acc0);
        acc1 = fmaf(a1[k].x, wv[k].x, acc1);
        acc1 = fmaf(a1[k].y, wv[k].y, acc1);
        acc1 = fmaf(a1[k].z, wv[k].z, acc1);
        acc1 = fmaf(a1[k].w, wv[k].w, acc1);
    }
    #pragma unroll
    for (int off = 16; off; off >>= 1) {
        acc0 += __shfl_xor_sync(0xffffffffu, acc0, off);
        acc1 += __shfl_xor_sync(0xffffffffu, acc1, off);
    }
    if (lane == 0) {
        float bv = bias[0];
        g_logits[row0]     = acc0 + bv;
        g_logits[row0 + 1] = acc1 + bv;
    }
}

// ---------------- Kernel 2: rank (stable) + skip softmax ----------------
__global__ void rank_kernel() {
    __shared__ float s[TT];
    __shared__ float skipP[NSKIP];
    __shared__ float skipE[NSKIP];

    int b = blockIdx.x;
    int i = threadIdx.x;

    if (i < TT) s[i] = g_logits[b*TT + i];
    __syncthreads();

    if (i < TT) {
        float my = s[i];
        int rank = 0;
        #pragma unroll 8
        for (int j = 0; j < TT; j++) {
            float v = s[j];
            rank += (v > my) || (v == my && j < i);  // stable: lower index wins
        }
        g_rank[b*TT + i] = rank;
        if (rank >= DENS) {
            int pos = (TT - 1) - rank;               // ascending skipped order
            g_skip[b*NSKIP + pos] = i;
            skipP[pos] = 1.f / (1.f + expf(-my));    // sigmoid prob
        }
    }
    __syncthreads();

    if (i < NSKIP) {
        float m = -1e30f;
        #pragma unroll
        for (int j = 0; j < NSKIP; j++) m = fmaxf(m, skipP[j]);
        skipE[i] = expf(skipP[i] - m);
    }
    __syncthreads();

    if (i < NSKIP) {
        float sum = 0.f;
        #pragma unroll
        for (int j = 0; j < NSKIP; j++) sum += skipE[j];
        g_weights[b*NSKIP + i] = skipE[i] / sum;
    }
}

// ---------------- Kernel 3: fused scatter + summary ----------------
// Blocks [0, BB)           : summary for batch blockIdx.x (long-latency, starts in wave 1, hidden)
// Blocks [BB, BB+rows/RPB) : scatter of RPB sequential source rows
__global__ void scatter_summary_kernel(const float* __restrict__ x, float* __restrict__ out) {
    const float4* xin = reinterpret_cast<const float4*>(x);
    float4* o4 = reinterpret_cast<float4*>(out);
    const size_t skipBase = (size_t)BB * DENS * D4;
    const size_t sumBase  = (size_t)BB * (DENS + NSKIP) * D4;
    int tid = threadIdx.x;              // 0..191

    if (blockIdx.x < BB) {
        // ---- summary path ----
        __shared__ int   sidx[NSKIP];
        __shared__ float swgt[NSKIP];
        int b = blockIdx.x;
        if (tid < NSKIP) {
            sidx[tid] = g_skip[b*NSKIP + tid];
            swgt[tid] = g_weights[b*NSKIP + tid];
        }
        __syncthreads();

        float4 acc = make_float4(0.f, 0.f, 0.f, 0.f);
        #pragma unroll 2
        for (int sI = 0; sI < NSKIP; sI++) {
            int src = sidx[sI];
            float wgt = swgt[sI];
            float4 vv = xin[((size_t)b*TT + src) * D4 + tid];
            acc.x = fmaf(wgt, vv.x, acc.x);
            acc.y = fmaf(wgt, vv.y, acc.y);
            acc.z = fmaf(wgt, vv.z, acc.z);
            acc.w = fmaf(wgt, vv.w, acc.w);
        }
        o4[sumBase + (size_t)b * D4 + tid] = acc;
    } else {
        // ---- scatter path ----
        int base = (blockIdx.x - BB) * RPB;   // first source row (global index b*TT+t)

        // Front-batched independent loads (MLP=8)
        float4 v[RPB];
        #pragma unroll
        for (int r = 0; r < RPB; r++)
            v[r] = xin[((size_t)(base + r)) * D4 + tid];

        #pragma unroll
        for (int r = 0; r < RPB; r++) {
            int src = base + r;
            int b = src / TT;
            int rank = g_rank[src];
            size_t off = (rank < DENS)
                ? ((size_t)(b*DENS + rank) * D4)
                : (skipBase + (size_t)(b*NSKIP + ((TT-1) - rank)) * D4);
            // streaming store: evict-first, keep x resident in L2
            __stcs(&o4[off + tid], v[r]);
        }
    }
}

extern "C" void kernel_launch(void* const* d_in, const int* in_sizes, int n_in,
                              void* d_out, int out_size) {
    const float* x    = (const float*)d_in[0];
    const float* w    = (const float*)d_in[1];
    const float* bias = (const float*)d_in[2];
    float* out = (float*)d_out;

    int rows = BB * TT;               // 36928
    // 1) logits: 2 rows per warp, 8 warps/block
    logits_kernel<<<(rows/2 + 7) / 8, 256>>>(x, w, bias);
    // 2) rank + softmax
    rank_kernel<<<BB, 608>>>();
    // 3) fused scatter (rows/RPB blocks) + summary (BB blocks, scheduled first)
    scatter_summary_kernel<<<BB + rows / RPB, 192>>>(x, out);
}

// round 5
// speedup vs baseline: 1.2491x; 1.0217x over previous
#include <cuda_runtime.h>

#define BB 64
#define TT 577
#define DD 768
#define DENS 519      // int(577*0.9)
#define NSKIP 58      // 577 - 519
#define D4 (DD/4)     // 192 float4 per row
#define RPB 8         // source rows per scatter block
#define NROWS (BB*TT) // 36928
#define NSCAT (NROWS/RPB) // 4616

// Scratch (no device allocation allowed)
__device__ float g_logits[NROWS];
__device__ int   g_rank[NROWS];      // rank (descending, stable) of each source row
__device__ int   g_skip[BB*NSKIP];   // per batch: skipped source indices, ascending prob order
__device__ float g_weights[BB*NSKIP];

// ---------------- Kernel 1: logits = x @ w + b  (one warp per TWO rows) ----------------
__global__ void logits_kernel(const float* __restrict__ x,
                              const float* __restrict__ w,
                              const float* __restrict__ bias) {
    int warpsPerBlock = blockDim.x >> 5;
    int warpId = threadIdx.x >> 5;
    int lane   = threadIdx.x & 31;
    int pair = blockIdx.x * warpsPerBlock + warpId;
    int row0 = pair * 2;
    if (row0 >= NROWS) return;

    const float4* xr0 = reinterpret_cast<const float4*>(x) + (size_t)row0 * D4;
    const float4* xr1 = xr0 + D4;
    const float4* w4  = reinterpret_cast<const float4*>(w);

    float4 a0[6], a1[6], wv[6];
    #pragma unroll
    for (int k = 0; k < 6; k++) a0[k] = xr0[k*32 + lane];
    #pragma unroll
    for (int k = 0; k < 6; k++) a1[k] = xr1[k*32 + lane];
    #pragma unroll
    for (int k = 0; k < 6; k++) wv[k] = __ldg(&w4[k*32 + lane]);

    float acc0 = 0.f, acc1 = 0.f;
    #pragma unroll
    for (int k = 0; k < 6; k++) {
        acc0 = fmaf(a0[k].x, wv[k].x, acc0);
        acc0 = fmaf(a0[k].y, wv[k].y, acc0);
        acc0 = fmaf(a0[k].z, wv[k].z, acc0);
        acc0 = fmaf(a0[k].w, wv[k].w, acc0);
        acc1 = fmaf(a1[k].x, wv[k].x, acc1);
        acc1 = fmaf(a1[k].y, wv[k].y, acc1);
        acc1 = fmaf(a1[k].z, wv[k].z, acc1);
        acc1 = fmaf(a1[k].w, wv[k].w, acc1);
    }
    #pragma unroll
    for (int off = 16; off; off >>= 1) {
        acc0 += __shfl_xor_sync(0xffffffffu, acc0, off);
        acc1 += __shfl_xor_sync(0xffffffffu, acc1, off);
    }
    if (lane == 0) {
        float bv = bias[0];
        g_logits[row0]     = acc0 + bv;
        g_logits[row0 + 1] = acc1 + bv;
    }
}

// ---------------- Kernel 2: rank (stable) + skip softmax ----------------
__global__ void rank_kernel() {
    __shared__ float s[TT];
    __shared__ float skipP[NSKIP];
    __shared__ float skipE[NSKIP];

    int b = blockIdx.x;
    int i = threadIdx.x;

    if (i < TT) s[i] = g_logits[b*TT + i];
    __syncthreads();

    if (i < TT) {
        float my = s[i];
        int rank = 0;
        #pragma unroll 8
        for (int j = 0; j < TT; j++) {
            float v = s[j];
            rank += (v > my) || (v == my && j < i);  // stable: lower index wins
        }
        g_rank[b*TT + i] = rank;
        if (rank >= DENS) {
            int pos = (TT - 1) - rank;               // ascending skipped order
            g_skip[b*NSKIP + pos] = i;
            skipP[pos] = 1.f / (1.f + expf(-my));    // sigmoid prob
        }
    }
    __syncthreads();

    if (i < NSKIP) {
        float m = -1e30f;
        #pragma unroll
        for (int j = 0; j < NSKIP; j++) m = fmaxf(m, skipP[j]);
        skipE[i] = expf(skipP[i] - m);
    }
    __syncthreads();

    if (i < NSKIP) {
        float sum = 0.f;
        #pragma unroll
        for (int j = 0; j < NSKIP; j++) sum += skipE[j];
        g_weights[b*NSKIP + i] = skipE[i] / sum;
    }
}

// ---------------- Kernel 3: fused scatter + summary ----------------
// Blocks [0, BB)           : summary for batch blockIdx.x (long-latency, starts first, hidden)
// Blocks [BB, BB+NSCAT)    : scatter RPB sequential source rows, REVERSED order
//                            (consume freshest L2 lines from logits pass first)
__global__ void scatter_summary_kernel(const float* __restrict__ x, float* __restrict__ out) {
    const float4* xin = reinterpret_cast<const float4*>(x);
    float4* o4 = reinterpret_cast<float4*>(out);
    const size_t skipBase = (size_t)BB * DENS * D4;
    const size_t sumBase  = (size_t)BB * (DENS + NSKIP) * D4;
    int tid = threadIdx.x;              // 0..191

    if (blockIdx.x < BB) {
        // ---- summary path ----
        __shared__ int   sidx[NSKIP];
        __shared__ float swgt[NSKIP];
        int b = blockIdx.x;
        if (tid < NSKIP) {
            sidx[tid] = g_skip[b*NSKIP + tid];
            swgt[tid] = g_weights[b*NSKIP + tid];
        }
        __syncthreads();

        float4 acc = make_float4(0.f, 0.f, 0.f, 0.f);
        #pragma unroll 2
        for (int sI = 0; sI < NSKIP; sI++) {
            int src = sidx[sI];
            float wgt = swgt[sI];
            float4 vv = xin[((size_t)b*TT + src) * D4 + tid];
            acc.x = fmaf(wgt, vv.x, acc.x);
            acc.y = fmaf(wgt, vv.y, acc.y);
            acc.z = fmaf(wgt, vv.z, acc.z);
            acc.w = fmaf(wgt, vv.w, acc.w);
        }
        o4[sumBase + (size_t)b * D4 + tid] = acc;
    } else {
        // ---- scatter path (reversed traversal: freshest L2 lines first) ----
        int sb = (NSCAT - 1) - (blockIdx.x - BB);
        int base = sb * RPB;            // first source row (global index b*TT+t)

        // Front-batched independent streaming loads (MLP=8, evict-first after use)
        float4 v[RPB];
        #pragma unroll
        for (int r = 0; r < RPB; r++)
            v[r] = __ldcs(&xin[((size_t)(base + r)) * D4 + tid]);

        #pragma unroll
        for (int r = 0; r < RPB; r++) {
            int src = base + r;
            int b = src / TT;
            int rank = g_rank[src];
            size_t off = (rank < DENS)
                ? ((size_t)(b*DENS + rank) * D4)
                : (skipBase + (size_t)(b*NSKIP + ((TT-1) - rank)) * D4);
            // streaming store: evict-first, don't displace x in L2
            __stcs(&o4[off + tid], v[r]);
        }
    }
}

extern "C" void kernel_launch(void* const* d_in, const int* in_sizes, int n_in,
                              void* d_out, int out_size) {
    const float* x    = (const float*)d_in[0];
    const float* w    = (const float*)d_in[1];
    const float* bias = (const float*)d_in[2];
    float* out = (float*)d_out;

    // 1) logits: 2 rows per warp, 8 warps/block
    logits_kernel<<<(NROWS/2 + 7) / 8, 256>>>(x, w, bias);
    // 2) rank + softmax
    rank_kernel<<<BB, 608>>>();
    // 3) fused scatter (reversed) + summary (first BB blocks)
    scatter_summary_kernel<<<BB + NSCAT, 192>>>(x, out);
}